// round 8
// baseline (speedup 1.0000x reference)
#include <cuda_runtime.h>
#include <stdint.h>
#include <math.h>

// Problem dims (dataset): N=100000 nodes, C=32 classes, E=3.2M edges
#define NMAX 100000
#define CC 32

// Scratch (device globals, zero-initialized at load; all state is
// self-resetting so repeated graph replays are deterministic).
__device__ float g_s[NMAX * CC];      // scatter matrix; ==0 at entry (dense resets rows it uses)
__device__ int2  g_info[NMAX];        // .x = bitcast(dinv), .y = label (-1 unmasked)
__device__ float g_deg[NMAX];         // ==0 at entry (node resets)
__device__ float g_H[CC * CC];        // ==0 at entry (final resets)
__device__ float g_cnt[CC];           // ==0 at entry (final resets)
__device__ float g_diag[CC];          // ==0 at entry (final resets)
__device__ int   g_maskmode;          // 0=uint8, 1=float32, 2=int32

__device__ __forceinline__ bool get_mask(const void* m, int r, int mm) {
    if (mm == 0) return ((const uint8_t*)m)[r] != 0;
    if (mm == 2) return ((const int*)m)[r] != 0;
    return ((const float*)m)[r] != 0.0f;
}

// ---------------------------------------------------------------------------
// deg += segment_sum(w, row); self-loop "+1" applied analytically later.
// Block 0 detects mask dtype (byte-mask viewed as int32/float32 can't be all
// {0,1}/{0.0f,1.0f}).
__global__ void deg_kernel(const int* __restrict__ row,
                           const float* __restrict__ w, int E,
                           const void* mask) {
    if (blockIdx.x == 0 && threadIdx.x == 0) {
        const int*   mi = (const int*)mask;
        const float* mf = (const float*)mask;
        bool isInt = true, isFloat = true;
        for (int k = 0; k < 64; k++) {
            int v = mi[k];
            if (v != 0 && v != 1) isInt = false;
            float f = mf[k];
            if (f != 0.0f && f != 1.0f) isFloat = false;
        }
        g_maskmode = isInt ? 2 : (isFloat ? 1 : 0);
    }
    int nvec   = E >> 2;
    int stride = gridDim.x * blockDim.x;
    for (int i = blockIdx.x * blockDim.x + threadIdx.x; i < nvec; i += stride) {
        int4   r4 = ((const int4*)row)[i];
        float4 w4 = ((const float4*)w)[i];
        atomicAdd(&g_deg[r4.x], w4.x);
        atomicAdd(&g_deg[r4.y], w4.y);
        atomicAdd(&g_deg[r4.z], w4.z);
        atomicAdd(&g_deg[r4.w], w4.w);
    }
    if (blockIdx.x == 0 && threadIdx.x < (E & 3)) {
        int e = (E & ~3) + threadIdx.x;
        atomicAdd(&g_deg[row[e]], w[e]);
    }
}

// 4 threads/node. Masked: label from y + cnt + diag(dinv^2). All: write info,
// reset g_deg[node]=0 (invariant for next replay).
__global__ void node_kernel(const float* __restrict__ y,
                            const void* mask, int N) {
    int tid  = blockIdx.x * blockDim.x + threadIdx.x;
    int node = tid >> 2;
    int sub  = tid & 3;
    if (node >= N) return;
    unsigned gm = 0xFu << (threadIdx.x & 28);   // 4-lane aligned group mask
    bool mk = get_mask(mask, node, g_maskmode);

    int labl = -1;
    if (mk) {
        const float4* yp = (const float4*)(y + node * CC) + sub * 2;
        float4 ya = yp[0], yb = yp[1];
        int bse = sub * 8;
        if (ya.x > 0.5f) labl = bse + 0;
        if (ya.y > 0.5f) labl = bse + 1;
        if (ya.z > 0.5f) labl = bse + 2;
        if (ya.w > 0.5f) labl = bse + 3;
        if (yb.x > 0.5f) labl = bse + 4;
        if (yb.y > 0.5f) labl = bse + 5;
        if (yb.z > 0.5f) labl = bse + 6;
        if (yb.w > 0.5f) labl = bse + 7;
        labl = max(labl, __shfl_xor_sync(gm, labl, 1));
        labl = max(labl, __shfl_xor_sync(gm, labl, 2));
    }

    if (sub == 0) {
        float d  = g_deg[node];
        g_deg[node] = 0.0f;
        float di = rsqrtf(1.0f + d);        // self-loop weight 1 included
        g_info[node] = make_int2(__float_as_int(di), mk ? labl : -1);
        if (mk) {
            atomicAdd(&g_cnt[labl], 1.0f);
            atomicAdd(&g_diag[labl], di * di);  // masked self-loop -> H[l][l]
        }
    }
}

// Edge scatter, mask-split. For masked-row edges, v = dinv_r * w * dinv_c:
//   col masked   -> scalar into per-block smem H tile [lab_r][lab_c]
//   col unmasked -> global atomic into s[col][lab_r]
__global__ void scatter_kernel(const int* __restrict__ row,
                               const int* __restrict__ col,
                               const float* __restrict__ w, int E) {
    __shared__ float sH[CC * 33];
    for (int k = threadIdx.x; k < CC * 33; k += blockDim.x) sH[k] = 0.0f;
    __syncthreads();

    int nvec   = E >> 2;
    int stride = gridDim.x * blockDim.x;
    for (int i = blockIdx.x * blockDim.x + threadIdx.x; i < nvec; i += stride) {
        int4   r4 = ((const int4*)row)[i];
        int4   c4 = ((const int4*)col)[i];
        float4 w4 = ((const float4*)w)[i];
        int2 i0 = g_info[r4.x];
        int2 i1 = g_info[r4.y];
        int2 i2 = g_info[r4.z];
        int2 i3 = g_info[r4.w];
        if (i0.y >= 0) {
            int2 ic = g_info[c4.x];
            float v = __int_as_float(i0.x) * w4.x * __int_as_float(ic.x);
            if (ic.y >= 0) atomicAdd(&sH[i0.y * 33 + ic.y], v);
            else           atomicAdd(&g_s[c4.x * CC + i0.y], v);
        }
        if (i1.y >= 0) {
            int2 ic = g_info[c4.y];
            float v = __int_as_float(i1.x) * w4.y * __int_as_float(ic.x);
            if (ic.y >= 0) atomicAdd(&sH[i1.y * 33 + ic.y], v);
            else           atomicAdd(&g_s[c4.y * CC + i1.y], v);
        }
        if (i2.y >= 0) {
            int2 ic = g_info[c4.z];
            float v = __int_as_float(i2.x) * w4.z * __int_as_float(ic.x);
            if (ic.y >= 0) atomicAdd(&sH[i2.y * 33 + ic.y], v);
            else           atomicAdd(&g_s[c4.z * CC + i2.y], v);
        }
        if (i3.y >= 0) {
            int2 ic = g_info[c4.w];
            float v = __int_as_float(i3.x) * w4.w * __int_as_float(ic.x);
            if (ic.y >= 0) atomicAdd(&sH[i3.y * 33 + ic.y], v);
            else           atomicAdd(&g_s[c4.w * CC + i3.y], v);
        }
    }
    if (blockIdx.x == 0 && threadIdx.x < (E & 3)) {
        int e = (E & ~3) + threadIdx.x;
        int r = row[e], c = col[e];
        int2 ir = g_info[r];
        if (ir.y >= 0) {
            int2 ic = g_info[c];
            float v = __int_as_float(ir.x) * w[e] * __int_as_float(ic.x);
            if (ic.y >= 0) atomicAdd(&sH[ir.y * 33 + ic.y], v);
            else           atomicAdd(&g_s[c * CC + ir.y], v);
        }
    }
    __syncthreads();
    for (int k = threadIdx.x; k < CC * CC; k += blockDim.x) {
        float v = sH[(k >> 5) * 33 + (k & 31)];
        if (v != 0.0f) atomicAdd(&g_H[k], v);
    }
}

// Dense rank-1 sum. Warp per row, 8-row batches (MLP=8). Softmax on the fly
// (no max-subtract: inputs ~N(0,1), exp safe). No launch-bounds register cap
// (acc[32] must stay in RF); larger grid for occupancy (reg-limited 4 blk/SM).
__global__ void dense_kernel(const float* __restrict__ inp, int N) {
    int wid  = threadIdx.x >> 5;
    int lane = threadIdx.x & 31;
    int gw     = blockIdx.x * 8 + wid;
    int nwarps = gridDim.x * 8;

    float acc[CC];
    #pragma unroll
    for (int a = 0; a < CC; a++) acc[a] = 0.0f;

    for (int base = gw * 8; base < N; base += nwarps * 8) {
        float sv[8];
        #pragma unroll
        for (int k = 0; k < 8; k++) {
            int c = base + k;
            sv[k] = (c < N) ? g_s[c * CC + lane] : 0.0f;   // 8 loads in flight
        }
        #pragma unroll
        for (int k = 0; k < 8; k++) {
            if (__ballot_sync(0xffffffffu, sv[k] != 0.0f)) {
                int c = base + k;
                float e = __expf(inp[c * CC + lane]);
                float s = e;
                #pragma unroll
                for (int o = 16; o; o >>= 1)
                    s += __shfl_xor_sync(0xffffffffu, s, o);
                float pv = e * __frcp_rn(s);
                #pragma unroll
                for (int a = 0; a < CC; a++)
                    acc[a] += __shfl_sync(0xffffffffu, sv[k], a) * pv;
                g_s[c * CC + lane] = 0.0f;     // self-clean for next replay
            }
        }
    }
    #pragma unroll
    for (int a = 0; a < CC; a++)
        atomicAdd(&g_H[a * CC + lane], acc[a]);
}

// Final: single warp, barrier-free. Lane j holds column j (h[i]=H[i][j]) AND
// row j (r[i]=H[j][i]) in registers. Sinkhorn to the fp32 fixed point of the
// reference's 3000 iterations. Convergence = periodic ENTRY-delta check (the
// iteration becomes bitwise idempotent at the fixed point; sum-based tests
// never fire because fp32 sums never equal exactly 1).
__global__ void final_kernel(float* __restrict__ out) {
    const unsigned F = 0xffffffffu;
    int j = threadIdx.x;

    float cnt_j  = g_cnt[j];
    float diag_j = g_diag[j];

    float h[CC], r[CC];
    #pragma unroll
    for (int i = 0; i < CC; i++) h[i] = g_H[i * CC + j];
    #pragma unroll
    for (int i = 0; i < CC; i++) r[i] = g_H[j * CC + i];
    #pragma unroll
    for (int i = 0; i < CC; i++)
        if (i == j) { h[i] += diag_j; r[i] += diag_j; }

    // H[i][:] /= cnt[i]  (0/0 -> NaN for empty classes)
    #pragma unroll
    for (int i = 0; i < CC; i++) {
        float ci = __shfl_sync(F, cnt_j, i);
        h[i] = h[i] / ci;          // column j entry of row i
        r[i] = r[i] / cnt_j;       // row j entries
    }

    // reset accumulators for next replay
    g_cnt[j] = 0.0f; g_diag[j] = 0.0f;
    #pragma unroll
    for (int i = 0; i < CC; i++) g_H[i * CC + j] = 0.0f;

    // Fixup 1: H = where(isnan(H), H^T, H) using ORIGINAL H on both sides.
    #pragma unroll
    for (int i = 0; i < CC; i++) {
        float hn = h[i], rn_ = r[i];
        h[i] = isnan(hn) ? rn_ : hn;
        r[i] = isnan(rn_) ? hn : rn_;
    }

    // Fixup 2 (row-wise): H0=where(nan,0,H); miss=(1-rowsum(H0))/nanCount
    float rs = 0.0f, rn = 0.0f;
    #pragma unroll
    for (int i = 0; i < CC; i++) {
        bool nn = isnan(r[i]);
        rs += nn ? 0.0f : r[i];
        rn += nn ? 1.0f : 0.0f;
    }
    float miss_j = (1.0f - rs) / rn;
    #pragma unroll
    for (int i = 0; i < CC; i++) {
        r[i] = isnan(r[i]) ? miss_j : r[i];
        float mi = __shfl_sync(F, miss_j, i);
        h[i] = isnan(h[i]) ? mi : h[i];
    }

    // Sinkhorn: col-normalize then row-normalize. Registers only.
    float hs[CC];
    #pragma unroll
    for (int i = 0; i < CC; i++) hs[i] = h[i];
    for (int it = 0; it < 3000; it++) {
        float cs = 0.0f;
        #pragma unroll
        for (int i = 0; i < CC; i++) cs += h[i];     // col j sum
        float cinv = 1.0f / cs;
        #pragma unroll
        for (int i = 0; i < CC; i++) {
            h[i] *= cinv;
            r[i] *= __shfl_sync(F, cinv, i);         // col i's scale
        }
        float rsum = 0.0f;
        #pragma unroll
        for (int i = 0; i < CC; i++) rsum += r[i];   // row j sum
        float rinv = 1.0f / rsum;
        #pragma unroll
        for (int i = 0; i < CC; i++) {
            r[i] *= rinv;
            h[i] *= __shfl_sync(F, rinv, i);         // row i's scale
        }
        if ((it & 7) == 7) {                          // entry-delta check
            float dev = 0.0f;
            #pragma unroll
            for (int i = 0; i < CC; i++) {
                dev = fmaxf(dev, fabsf(h[i] - hs[i]));
                hs[i] = h[i];
            }
            #pragma unroll
            for (int o = 16; o; o >>= 1)
                dev = fmaxf(dev, __shfl_xor_sync(F, dev, o));
            if (dev < 1e-9f) break;
        }
    }

    #pragma unroll
    for (int i = 0; i < CC; i++) out[i * CC + j] = h[i];
}

// ---------------------------------------------------------------------------
extern "C" void kernel_launch(void* const* d_in, const int* in_sizes, int n_in,
                              void* d_out, int out_size) {
    const int*   ei   = (const int*)d_in[0];    // edge_index (2,E)
    const float* ew   = (const float*)d_in[1];  // edge_weight (E,)
    const float* inp  = (const float*)d_in[2];  // inputs (N,32)
    const float* y    = (const float*)d_in[3];  // y (N,32)
    const void*  mask = d_in[4];                // sample_mask (N,)

    int E = in_sizes[1];
    int N = in_sizes[2] / CC;
    const int* rowp = ei;
    const int* colp = ei + E;

    deg_kernel<<<1184, 256>>>(rowp, ew, E, mask);
    node_kernel<<<(N * 4 + 255) / 256, 256>>>(y, mask, N);
    scatter_kernel<<<888, 256>>>(rowp, colp, ew, E);
    dense_kernel<<<1184, 256>>>(inp, N);
    final_kernel<<<1, 32>>>((float*)d_out);
}

// round 10
// speedup vs baseline: 13.3227x; 13.3227x over previous
#include <cuda_runtime.h>
#include <stdint.h>
#include <math.h>

// Problem dims (dataset): N=100000 nodes, C=32 classes, E=3.2M edges
#define NMAX 100000
#define CC 32

// Scratch (device globals, zero-initialized at load; all state is
// self-resetting so repeated graph replays are deterministic).
__device__ float g_s[NMAX * CC];      // scatter matrix; ==0 at entry (dense resets rows it uses)
__device__ int2  g_info[NMAX];        // .x = bitcast(dinv), .y = label (-1 unmasked)
__device__ float g_deg[NMAX];         // ==0 at entry (node resets)
__device__ float g_H[CC * CC];        // ==0 at entry (final resets)
__device__ float g_cnt[CC];           // ==0 at entry (final resets)
__device__ float g_diag[CC];          // ==0 at entry (final resets)
__device__ int   g_maskmode;          // 0=uint8, 1=float32, 2=int32

__device__ __forceinline__ bool get_mask(const void* m, int r, int mm) {
    if (mm == 0) return ((const uint8_t*)m)[r] != 0;
    if (mm == 2) return ((const int*)m)[r] != 0;
    return ((const float*)m)[r] != 0.0f;
}

// ---------------------------------------------------------------------------
// deg += segment_sum(w, row); self-loop "+1" applied analytically later.
// Block 0 detects mask dtype (byte-mask viewed as int32/float32 can't be all
// {0,1}/{0.0f,1.0f}).
__global__ void deg_kernel(const int* __restrict__ row,
                           const float* __restrict__ w, int E,
                           const void* mask) {
    if (blockIdx.x == 0 && threadIdx.x == 0) {
        const int*   mi = (const int*)mask;
        const float* mf = (const float*)mask;
        bool isInt = true, isFloat = true;
        for (int k = 0; k < 64; k++) {
            int v = mi[k];
            if (v != 0 && v != 1) isInt = false;
            float f = mf[k];
            if (f != 0.0f && f != 1.0f) isFloat = false;
        }
        g_maskmode = isInt ? 2 : (isFloat ? 1 : 0);
    }
    int nvec   = E >> 2;
    int stride = gridDim.x * blockDim.x;
    for (int i = blockIdx.x * blockDim.x + threadIdx.x; i < nvec; i += stride) {
        int4   r4 = ((const int4*)row)[i];
        float4 w4 = ((const float4*)w)[i];
        atomicAdd(&g_deg[r4.x], w4.x);
        atomicAdd(&g_deg[r4.y], w4.y);
        atomicAdd(&g_deg[r4.z], w4.z);
        atomicAdd(&g_deg[r4.w], w4.w);
    }
    if (blockIdx.x == 0 && threadIdx.x < (E & 3)) {
        int e = (E & ~3) + threadIdx.x;
        atomicAdd(&g_deg[row[e]], w[e]);
    }
}

// 4 threads/node. Masked: label from y + cnt + diag(dinv^2). All: write info,
// reset g_deg[node]=0 (invariant for next replay).
__global__ void node_kernel(const float* __restrict__ y,
                            const void* mask, int N) {
    int tid  = blockIdx.x * blockDim.x + threadIdx.x;
    int node = tid >> 2;
    int sub  = tid & 3;
    if (node >= N) return;
    unsigned gm = 0xFu << (threadIdx.x & 28);   // 4-lane aligned group mask
    bool mk = get_mask(mask, node, g_maskmode);

    int labl = -1;
    if (mk) {
        const float4* yp = (const float4*)(y + node * CC) + sub * 2;
        float4 ya = yp[0], yb = yp[1];
        int bse = sub * 8;
        if (ya.x > 0.5f) labl = bse + 0;
        if (ya.y > 0.5f) labl = bse + 1;
        if (ya.z > 0.5f) labl = bse + 2;
        if (ya.w > 0.5f) labl = bse + 3;
        if (yb.x > 0.5f) labl = bse + 4;
        if (yb.y > 0.5f) labl = bse + 5;
        if (yb.z > 0.5f) labl = bse + 6;
        if (yb.w > 0.5f) labl = bse + 7;
        labl = max(labl, __shfl_xor_sync(gm, labl, 1));
        labl = max(labl, __shfl_xor_sync(gm, labl, 2));
    }

    if (sub == 0) {
        float d  = g_deg[node];
        g_deg[node] = 0.0f;
        float di = rsqrtf(1.0f + d);        // self-loop weight 1 included
        g_info[node] = make_int2(__float_as_int(di), mk ? labl : -1);
        if (mk) {
            atomicAdd(&g_cnt[labl], 1.0f);
            atomicAdd(&g_diag[labl], di * di);  // masked self-loop -> H[l][l]
        }
    }
}

// Edge scatter, mask-split. For masked-row edges, v = dinv_r * w * dinv_c:
//   col masked   -> scalar into per-block smem H tile [lab_r][lab_c]
//   col unmasked -> global atomic into s[col][lab_r]
__global__ void scatter_kernel(const int* __restrict__ row,
                               const int* __restrict__ col,
                               const float* __restrict__ w, int E) {
    __shared__ float sH[CC * 33];
    for (int k = threadIdx.x; k < CC * 33; k += blockDim.x) sH[k] = 0.0f;
    __syncthreads();

    int nvec   = E >> 2;
    int stride = gridDim.x * blockDim.x;
    for (int i = blockIdx.x * blockDim.x + threadIdx.x; i < nvec; i += stride) {
        int4   r4 = ((const int4*)row)[i];
        int4   c4 = ((const int4*)col)[i];
        float4 w4 = ((const float4*)w)[i];
        int2 i0 = g_info[r4.x];
        int2 i1 = g_info[r4.y];
        int2 i2 = g_info[r4.z];
        int2 i3 = g_info[r4.w];
        if (i0.y >= 0) {
            int2 ic = g_info[c4.x];
            float v = __int_as_float(i0.x) * w4.x * __int_as_float(ic.x);
            if (ic.y >= 0) atomicAdd(&sH[i0.y * 33 + ic.y], v);
            else           atomicAdd(&g_s[c4.x * CC + i0.y], v);
        }
        if (i1.y >= 0) {
            int2 ic = g_info[c4.y];
            float v = __int_as_float(i1.x) * w4.y * __int_as_float(ic.x);
            if (ic.y >= 0) atomicAdd(&sH[i1.y * 33 + ic.y], v);
            else           atomicAdd(&g_s[c4.y * CC + i1.y], v);
        }
        if (i2.y >= 0) {
            int2 ic = g_info[c4.z];
            float v = __int_as_float(i2.x) * w4.z * __int_as_float(ic.x);
            if (ic.y >= 0) atomicAdd(&sH[i2.y * 33 + ic.y], v);
            else           atomicAdd(&g_s[c4.z * CC + i2.y], v);
        }
        if (i3.y >= 0) {
            int2 ic = g_info[c4.w];
            float v = __int_as_float(i3.x) * w4.w * __int_as_float(ic.x);
            if (ic.y >= 0) atomicAdd(&sH[i3.y * 33 + ic.y], v);
            else           atomicAdd(&g_s[c4.w * CC + i3.y], v);
        }
    }
    if (blockIdx.x == 0 && threadIdx.x < (E & 3)) {
        int e = (E & ~3) + threadIdx.x;
        int r = row[e], c = col[e];
        int2 ir = g_info[r];
        if (ir.y >= 0) {
            int2 ic = g_info[c];
            float v = __int_as_float(ir.x) * w[e] * __int_as_float(ic.x);
            if (ic.y >= 0) atomicAdd(&sH[ir.y * 33 + ic.y], v);
            else           atomicAdd(&g_s[c * CC + ir.y], v);
        }
    }
    __syncthreads();
    for (int k = threadIdx.x; k < CC * CC; k += blockDim.x) {
        float v = sH[(k >> 5) * 33 + (k & 31)];
        if (v != 0.0f) atomicAdd(&g_H[k], v);
    }
}

// Dense rank-1 sum. Warp per row, 8-row batches (MLP=8). Softmax on the fly.
// Per-warp acc stays in registers; flush is hierarchical: smem block reduction
// then ONE 1024-cell global atomic set per block (global atomic lane-ops scale
// with #blocks, not #warps — the R8 per-warp flush serialized at L2).
__global__ void dense_kernel(const float* __restrict__ inp, int N) {
    __shared__ float sacc[8][CC * CC];    // 32 KB
    int wid  = threadIdx.x >> 5;
    int lane = threadIdx.x & 31;
    int gw     = blockIdx.x * 8 + wid;
    int nwarps = gridDim.x * 8;

    float acc[CC];
    #pragma unroll
    for (int a = 0; a < CC; a++) acc[a] = 0.0f;

    for (int base = gw * 8; base < N; base += nwarps * 8) {
        float sv[8];
        #pragma unroll
        for (int k = 0; k < 8; k++) {
            int c = base + k;
            sv[k] = (c < N) ? g_s[c * CC + lane] : 0.0f;   // 8 loads in flight
        }
        #pragma unroll
        for (int k = 0; k < 8; k++) {
            if (__ballot_sync(0xffffffffu, sv[k] != 0.0f)) {
                int c = base + k;
                float e = __expf(inp[c * CC + lane]);
                float s = e;
                #pragma unroll
                for (int o = 16; o; o >>= 1)
                    s += __shfl_xor_sync(0xffffffffu, s, o);
                float pv = e * __frcp_rn(s);
                #pragma unroll
                for (int a = 0; a < CC; a++)
                    acc[a] += __shfl_sync(0xffffffffu, sv[k], a) * pv;
                g_s[c * CC + lane] = 0.0f;     // self-clean for next replay
            }
        }
    }
    // hierarchical flush
    #pragma unroll
    for (int a = 0; a < CC; a++) sacc[wid][a * CC + lane] = acc[a];
    __syncthreads();
    for (int k = threadIdx.x; k < CC * CC; k += blockDim.x) {
        float s = 0.0f;
        #pragma unroll
        for (int ww = 0; ww < 8; ww++) s += sacc[ww][k];
        if (s != 0.0f) atomicAdd(&g_H[k], s);
    }
}

// Final: single warp, barrier-free. Lane j holds column j (h[i]=H[i][j]) AND
// row j (r[i]=H[j][i]) in registers. Sinkhorn to the fp32 fixed point of the
// reference's 3000 iterations. Convergence = periodic entry-delta check with
// threshold 4e-8: ABOVE the ~1-2 ulp limit-cycle amplitude of entries ~1/32
// (ulp ~3.7e-9; the 1e-9 threshold of R8 could never fire).
__global__ void final_kernel(float* __restrict__ out) {
    const unsigned F = 0xffffffffu;
    int j = threadIdx.x;

    float cnt_j  = g_cnt[j];
    float diag_j = g_diag[j];

    float h[CC], r[CC];
    #pragma unroll
    for (int i = 0; i < CC; i++) h[i] = g_H[i * CC + j];
    #pragma unroll
    for (int i = 0; i < CC; i++) r[i] = g_H[j * CC + i];
    #pragma unroll
    for (int i = 0; i < CC; i++)
        if (i == j) { h[i] += diag_j; r[i] += diag_j; }

    // H[i][:] /= cnt[i]  (0/0 -> NaN for empty classes)
    #pragma unroll
    for (int i = 0; i < CC; i++) {
        float ci = __shfl_sync(F, cnt_j, i);
        h[i] = h[i] / ci;          // column j entry of row i
        r[i] = r[i] / cnt_j;       // row j entries
    }

    // reset accumulators for next replay
    g_cnt[j] = 0.0f; g_diag[j] = 0.0f;
    #pragma unroll
    for (int i = 0; i < CC; i++) g_H[i * CC + j] = 0.0f;

    // Fixup 1: H = where(isnan(H), H^T, H) using ORIGINAL H on both sides.
    #pragma unroll
    for (int i = 0; i < CC; i++) {
        float hn = h[i], rn_ = r[i];
        h[i] = isnan(hn) ? rn_ : hn;
        r[i] = isnan(rn_) ? hn : rn_;
    }

    // Fixup 2 (row-wise): H0=where(nan,0,H); miss=(1-rowsum(H0))/nanCount
    float rs = 0.0f, rn = 0.0f;
    #pragma unroll
    for (int i = 0; i < CC; i++) {
        bool nn = isnan(r[i]);
        rs += nn ? 0.0f : r[i];
        rn += nn ? 1.0f : 0.0f;
    }
    float miss_j = (1.0f - rs) / rn;
    #pragma unroll
    for (int i = 0; i < CC; i++) {
        r[i] = isnan(r[i]) ? miss_j : r[i];
        float mi = __shfl_sync(F, miss_j, i);
        h[i] = isnan(h[i]) ? mi : h[i];
    }

    // Sinkhorn: col-normalize then row-normalize. Registers only.
    float hs[CC];
    #pragma unroll
    for (int i = 0; i < CC; i++) hs[i] = h[i];
    for (int it = 0; it < 3000; it++) {
        float cs = 0.0f;
        #pragma unroll
        for (int i = 0; i < CC; i++) cs += h[i];     // col j sum
        float cinv = 1.0f / cs;
        #pragma unroll
        for (int i = 0; i < CC; i++) {
            h[i] *= cinv;
            r[i] *= __shfl_sync(F, cinv, i);         // col i's scale
        }
        float rsum = 0.0f;
        #pragma unroll
        for (int i = 0; i < CC; i++) rsum += r[i];   // row j sum
        float rinv = 1.0f / rsum;
        #pragma unroll
        for (int i = 0; i < CC; i++) {
            r[i] *= rinv;
            h[i] *= __shfl_sync(F, rinv, i);         // row i's scale
        }
        if ((it & 7) == 7) {                          // entry-delta check
            float dev = 0.0f;
            #pragma unroll
            for (int i = 0; i < CC; i++) {
                dev = fmaxf(dev, fabsf(h[i] - hs[i]));
                hs[i] = h[i];
            }
            #pragma unroll
            for (int o = 16; o; o >>= 1)
                dev = fmaxf(dev, __shfl_xor_sync(F, dev, o));
            if (dev < 4e-8f) break;
        }
    }

    #pragma unroll
    for (int i = 0; i < CC; i++) out[i * CC + j] = h[i];
}

// ---------------------------------------------------------------------------
extern "C" void kernel_launch(void* const* d_in, const int* in_sizes, int n_in,
                              void* d_out, int out_size) {
    const int*   ei   = (const int*)d_in[0];    // edge_index (2,E)
    const float* ew   = (const float*)d_in[1];  // edge_weight (E,)
    const float* inp  = (const float*)d_in[2];  // inputs (N,32)
    const float* y    = (const float*)d_in[3];  // y (N,32)
    const void*  mask = d_in[4];                // sample_mask (N,)

    int E = in_sizes[1];
    int N = in_sizes[2] / CC;
    const int* rowp = ei;
    const int* colp = ei + E;

    deg_kernel<<<1184, 256>>>(rowp, ew, E, mask);
    node_kernel<<<(N * 4 + 255) / 256, 256>>>(y, mask, N);
    scatter_kernel<<<888, 256>>>(rowp, colp, ew, E);
    dense_kernel<<<592, 256>>>(inp, N);
    final_kernel<<<1, 32>>>((float*)d_out);
}

// round 12
// speedup vs baseline: 13.7158x; 1.0295x over previous
#include <cuda_runtime.h>
#include <stdint.h>
#include <math.h>

// Problem dims (dataset): N=100000 nodes, C=32 classes, E=3.2M edges
#define NMAX 100000
#define CC 32

// Scratch (device globals, zero-initialized at load; all state is
// self-resetting so repeated graph replays are deterministic).
__device__ float g_s[NMAX * CC];      // scatter matrix; ==0 at entry (dense resets rows it uses)
__device__ int2  g_info[NMAX];        // .x = bitcast(dinv), .y = label (-1 unmasked)
__device__ int   g_list[NMAX];        // compact list of unmasked node ids
__device__ float g_deg[NMAX];         // ==0 at entry (node resets)
__device__ float g_H[CC * CC];        // ==0 at entry (final resets)
__device__ float g_cnt[CC];           // ==0 at entry (final resets)
__device__ float g_diag[CC];          // ==0 at entry (final resets)
__device__ int   g_nu;                // ==0 at entry (final resets); # unmasked nodes
__device__ int   g_maskmode;          // 0=uint8, 1=float32, 2=int32

__device__ __forceinline__ bool get_mask(const void* m, int r, int mm) {
    if (mm == 0) return ((const uint8_t*)m)[r] != 0;
    if (mm == 2) return ((const int*)m)[r] != 0;
    return ((const float*)m)[r] != 0.0f;
}

// ---------------------------------------------------------------------------
// deg += segment_sum(w, row); self-loop "+1" applied analytically later.
// Block 0 detects mask dtype (byte-mask viewed as int32/float32 can't be all
// {0,1}/{0.0f,1.0f}).
__global__ void deg_kernel(const int* __restrict__ row,
                           const float* __restrict__ w, int E,
                           const void* mask) {
    if (blockIdx.x == 0 && threadIdx.x == 0) {
        const int*   mi = (const int*)mask;
        const float* mf = (const float*)mask;
        bool isInt = true, isFloat = true;
        for (int k = 0; k < 64; k++) {
            int v = mi[k];
            if (v != 0 && v != 1) isInt = false;
            float f = mf[k];
            if (f != 0.0f && f != 1.0f) isFloat = false;
        }
        g_maskmode = isInt ? 2 : (isFloat ? 1 : 0);
    }
    int nvec   = E >> 2;
    int stride = gridDim.x * blockDim.x;
    for (int i = blockIdx.x * blockDim.x + threadIdx.x; i < nvec; i += stride) {
        int4   r4 = ((const int4*)row)[i];
        float4 w4 = ((const float4*)w)[i];
        atomicAdd(&g_deg[r4.x], w4.x);
        atomicAdd(&g_deg[r4.y], w4.y);
        atomicAdd(&g_deg[r4.z], w4.z);
        atomicAdd(&g_deg[r4.w], w4.w);
    }
    if (blockIdx.x == 0 && threadIdx.x < (E & 3)) {
        int e = (E & ~3) + threadIdx.x;
        atomicAdd(&g_deg[row[e]], w[e]);
    }
}

// 4 threads/node. Masked: label from y + cnt + diag(dinv^2). Unmasked: append
// node id to compact list (warp-aggregated atomic). All: write info, reset
// g_deg[node]=0 (invariant for next replay).
__global__ void node_kernel(const float* __restrict__ y,
                            const void* mask, int N) {
    const unsigned F = 0xffffffffu;
    int tid  = blockIdx.x * blockDim.x + threadIdx.x;
    int node = tid >> 2;
    int sub  = tid & 3;
    int lane = threadIdx.x & 31;
    bool valid = (node < N);
    unsigned gm = 0xFu << (threadIdx.x & 28);   // 4-lane aligned group mask
    bool mk = valid ? get_mask(mask, node, g_maskmode) : false;

    int labl = -1;
    if (valid && mk) {
        const float4* yp = (const float4*)(y + node * CC) + sub * 2;
        float4 ya = yp[0], yb = yp[1];
        int bse = sub * 8;
        if (ya.x > 0.5f) labl = bse + 0;
        if (ya.y > 0.5f) labl = bse + 1;
        if (ya.z > 0.5f) labl = bse + 2;
        if (ya.w > 0.5f) labl = bse + 3;
        if (yb.x > 0.5f) labl = bse + 4;
        if (yb.y > 0.5f) labl = bse + 5;
        if (yb.z > 0.5f) labl = bse + 6;
        if (yb.w > 0.5f) labl = bse + 7;
    }
    labl = max(labl, __shfl_xor_sync(F, labl, 1));
    labl = max(labl, __shfl_xor_sync(F, labl, 2));

    // warp-aggregated append of unmasked node ids (one atomic per warp)
    unsigned um = __ballot_sync(F, valid && !mk && sub == 0);
    int base = 0;
    if (lane == 0 && um) base = atomicAdd(&g_nu, __popc(um));
    base = __shfl_sync(F, base, 0);
    if (valid && !mk && sub == 0)
        g_list[base + __popc(um & ((1u << lane) - 1u))] = node;

    if (valid && sub == 0) {
        float d  = g_deg[node];
        g_deg[node] = 0.0f;
        float di = rsqrtf(1.0f + d);        // self-loop weight 1 included
        g_info[node] = make_int2(__float_as_int(di), mk ? labl : -1);
        if (mk) {
            atomicAdd(&g_cnt[labl], 1.0f);
            atomicAdd(&g_diag[labl], di * di);  // masked self-loop -> H[l][l]
        }
    }
}

// Edge scatter, mask-split. For masked-row edges, v = dinv_r * w * dinv_c:
//   col masked   -> scalar into per-block smem H tile [lab_r][lab_c]
//   col unmasked -> global atomic into s[col][lab_r]
__global__ void scatter_kernel(const int* __restrict__ row,
                               const int* __restrict__ col,
                               const float* __restrict__ w, int E) {
    __shared__ float sH[CC * 33];
    for (int k = threadIdx.x; k < CC * 33; k += blockDim.x) sH[k] = 0.0f;
    __syncthreads();

    int nvec   = E >> 2;
    int stride = gridDim.x * blockDim.x;
    for (int i = blockIdx.x * blockDim.x + threadIdx.x; i < nvec; i += stride) {
        int4   r4 = ((const int4*)row)[i];
        int4   c4 = ((const int4*)col)[i];
        float4 w4 = ((const float4*)w)[i];
        int2 i0 = g_info[r4.x];
        int2 i1 = g_info[r4.y];
        int2 i2 = g_info[r4.z];
        int2 i3 = g_info[r4.w];
        if (i0.y >= 0) {
            int2 ic = g_info[c4.x];
            float v = __int_as_float(i0.x) * w4.x * __int_as_float(ic.x);
            if (ic.y >= 0) atomicAdd(&sH[i0.y * 33 + ic.y], v);
            else           atomicAdd(&g_s[c4.x * CC + i0.y], v);
        }
        if (i1.y >= 0) {
            int2 ic = g_info[c4.y];
            float v = __int_as_float(i1.x) * w4.y * __int_as_float(ic.x);
            if (ic.y >= 0) atomicAdd(&sH[i1.y * 33 + ic.y], v);
            else           atomicAdd(&g_s[c4.y * CC + i1.y], v);
        }
        if (i2.y >= 0) {
            int2 ic = g_info[c4.z];
            float v = __int_as_float(i2.x) * w4.z * __int_as_float(ic.x);
            if (ic.y >= 0) atomicAdd(&sH[i2.y * 33 + ic.y], v);
            else           atomicAdd(&g_s[c4.z * CC + i2.y], v);
        }
        if (i3.y >= 0) {
            int2 ic = g_info[c4.w];
            float v = __int_as_float(i3.x) * w4.w * __int_as_float(ic.x);
            if (ic.y >= 0) atomicAdd(&sH[i3.y * 33 + ic.y], v);
            else           atomicAdd(&g_s[c4.w * CC + i3.y], v);
        }
    }
    if (blockIdx.x == 0 && threadIdx.x < (E & 3)) {
        int e = (E & ~3) + threadIdx.x;
        int r = row[e], c = col[e];
        int2 ir = g_info[r];
        if (ir.y >= 0) {
            int2 ic = g_info[c];
            float v = __int_as_float(ir.x) * w[e] * __int_as_float(ic.x);
            if (ic.y >= 0) atomicAdd(&sH[ir.y * 33 + ic.y], v);
            else           atomicAdd(&g_s[c * CC + ir.y], v);
        }
    }
    __syncthreads();
    for (int k = threadIdx.x; k < CC * CC; k += blockDim.x) {
        float v = sH[(k >> 5) * 33 + (k & 31)];
        if (v != 0.0f) atomicAdd(&g_H[k], v);
    }
}

// Dense rank-1 sum over the COMPACT unmasked-node list (no wasted zero-row
// streaming). 8 rows/warp/batch, s+inp prefetched (MLP=16). Softmax on the
// fly; s rows zeroed after use. Hierarchical flush (block smem reduce, one
// global atomic set per block).
__global__ void dense_kernel(const float* __restrict__ inp) {
    const unsigned F = 0xffffffffu;
    __shared__ float sacc[8][CC * CC];    // 32 KB
    int wid  = threadIdx.x >> 5;
    int lane = threadIdx.x & 31;
    int gw     = blockIdx.x * 8 + wid;
    int nwarps = gridDim.x * 8;
    int M = g_nu;

    float acc[CC];
    #pragma unroll
    for (int a = 0; a < CC; a++) acc[a] = 0.0f;

    for (int base = gw * 8; base < M; base += nwarps * 8) {
        int idx = base + lane;
        int nid = (lane < 8 && idx < M) ? g_list[idx] : -1;
        float sv[8], xv[8];
        #pragma unroll
        for (int k = 0; k < 8; k++) {               // 16 loads in flight
            int n = __shfl_sync(F, nid, k);
            sv[k] = (n >= 0) ? g_s[n * CC + lane] : 0.0f;
            xv[k] = (n >= 0) ? inp[n * CC + lane] : 0.0f;
        }
        #pragma unroll
        for (int k = 0; k < 8; k++) {
            int n = __shfl_sync(F, nid, k);
            if (n >= 0) {
                float e = __expf(xv[k]);
                float s = e;
                #pragma unroll
                for (int o = 16; o; o >>= 1)
                    s += __shfl_xor_sync(F, s, o);
                float pv = e * __frcp_rn(s);
                #pragma unroll
                for (int a = 0; a < CC; a++)
                    acc[a] += __shfl_sync(F, sv[k], a) * pv;
                g_s[n * CC + lane] = 0.0f;     // self-clean for next replay
            }
        }
    }
    // hierarchical flush
    #pragma unroll
    for (int a = 0; a < CC; a++) sacc[wid][a * CC + lane] = acc[a];
    __syncthreads();
    for (int k = threadIdx.x; k < CC * CC; k += blockDim.x) {
        float s = 0.0f;
        #pragma unroll
        for (int ww = 0; ww < 8; ww++) s += sacc[ww][k];
        if (s != 0.0f) atomicAdd(&g_H[k], s);
    }
}

// Final: single warp, barrier-free, ISSUE-bound -> minimize instructions:
// balanced tree sums (not serial chains), __fdividef reciprocals, convergence
// check every 4 iters at 1e-7 entry-delta (above the ~1.5e-8 limit-cycle of
// entries ~1/32; early-stop residual ~1e-6 abs << 1e-3 tolerance).
__global__ void final_kernel(float* __restrict__ out) {
    const unsigned F = 0xffffffffu;
    int j = threadIdx.x;

    float cnt_j  = g_cnt[j];
    float diag_j = g_diag[j];

    float h[CC], r[CC];
    #pragma unroll
    for (int i = 0; i < CC; i++) h[i] = g_H[i * CC + j];
    #pragma unroll
    for (int i = 0; i < CC; i++) r[i] = g_H[j * CC + i];
    #pragma unroll
    for (int i = 0; i < CC; i++)
        if (i == j) { h[i] += diag_j; r[i] += diag_j; }

    // H[i][:] /= cnt[i]  (0/0 -> NaN for empty classes)
    #pragma unroll
    for (int i = 0; i < CC; i++) {
        float ci = __shfl_sync(F, cnt_j, i);
        h[i] = h[i] / ci;          // column j entry of row i
        r[i] = r[i] / cnt_j;       // row j entries
    }

    // reset accumulators for next replay
    g_cnt[j] = 0.0f; g_diag[j] = 0.0f;
    if (j == 0) g_nu = 0;
    #pragma unroll
    for (int i = 0; i < CC; i++) g_H[i * CC + j] = 0.0f;

    // Fixup 1: H = where(isnan(H), H^T, H) using ORIGINAL H on both sides.
    #pragma unroll
    for (int i = 0; i < CC; i++) {
        float hn = h[i], rn_ = r[i];
        h[i] = isnan(hn) ? rn_ : hn;
        r[i] = isnan(rn_) ? hn : rn_;
    }

    // Fixup 2 (row-wise): H0=where(nan,0,H); miss=(1-rowsum(H0))/nanCount
    float rs = 0.0f, rn = 0.0f;
    #pragma unroll
    for (int i = 0; i < CC; i++) {
        bool nn = isnan(r[i]);
        rs += nn ? 0.0f : r[i];
        rn += nn ? 1.0f : 0.0f;
    }
    float miss_j = (1.0f - rs) / rn;
    #pragma unroll
    for (int i = 0; i < CC; i++) {
        r[i] = isnan(r[i]) ? miss_j : r[i];
        float mi = __shfl_sync(F, miss_j, i);
        h[i] = isnan(h[i]) ? mi : h[i];
    }

    // Sinkhorn: col-normalize then row-normalize. Registers only.
    float hs[CC];
    #pragma unroll
    for (int i = 0; i < CC; i++) hs[i] = h[i];
    float t[CC];
    for (int it = 0; it < 3000; it++) {
        // balanced tree col sum (depth 5)
        #pragma unroll
        for (int i = 0; i < CC; i++) t[i] = h[i];
        #pragma unroll
        for (int st = 16; st; st >>= 1)
            #pragma unroll
            for (int i = 0; i < 16; i++)
                if (i < st) t[i] += t[i + st];
        float cinv = __fdividef(1.0f, t[0]);
        #pragma unroll
        for (int i = 0; i < CC; i++) {
            h[i] *= cinv;
            r[i] *= __shfl_sync(F, cinv, i);         // col i's scale
        }
        // balanced tree row sum
        #pragma unroll
        for (int i = 0; i < CC; i++) t[i] = r[i];
        #pragma unroll
        for (int st = 16; st; st >>= 1)
            #pragma unroll
            for (int i = 0; i < 16; i++)
                if (i < st) t[i] += t[i + st];
        float rinv = __fdividef(1.0f, t[0]);
        #pragma unroll
        for (int i = 0; i < CC; i++) {
            r[i] *= rinv;
            h[i] *= __shfl_sync(F, rinv, i);         // row i's scale
        }
        if ((it & 3) == 3) {                          // entry-delta check
            float dev = 0.0f;
            #pragma unroll
            for (int i = 0; i < CC; i++) {
                dev = fmaxf(dev, fabsf(h[i] - hs[i]));
                hs[i] = h[i];
            }
            #pragma unroll
            for (int o = 16; o; o >>= 1)
                dev = fmaxf(dev, __shfl_xor_sync(F, dev, o));
            if (dev < 1e-7f) break;
        }
    }

    #pragma unroll
    for (int i = 0; i < CC; i++) out[i * CC + j] = h[i];
}

// ---------------------------------------------------------------------------
extern "C" void kernel_launch(void* const* d_in, const int* in_sizes, int n_in,
                              void* d_out, int out_size) {
    const int*   ei   = (const int*)d_in[0];    // edge_index (2,E)
    const float* ew   = (const float*)d_in[1];  // edge_weight (E,)
    const float* inp  = (const float*)d_in[2];  // inputs (N,32)
    const float* y    = (const float*)d_in[3];  // y (N,32)
    const void*  mask = d_in[4];                // sample_mask (N,)

    int E = in_sizes[1];
    int N = in_sizes[2] / CC;
    const int* rowp = ei;
    const int* colp = ei + E;

    deg_kernel<<<1184, 256>>>(rowp, ew, E, mask);
    node_kernel<<<(N * 4 + 255) / 256, 256>>>(y, mask, N);
    scatter_kernel<<<1184, 256>>>(rowp, colp, ew, E);
    dense_kernel<<<592, 256>>>(inp);
    final_kernel<<<1, 32>>>((float*)d_out);
}